// round 1
// baseline (speedup 1.0000x reference)
#include <cuda_runtime.h>
#include <cstdint>
#include <cstddef>

typedef unsigned long long ull;

// ---------------- scratch (static device globals; no runtime alloc) ----------
__device__ float g_Wh[8192 * 256];   // [b*1024+n][h*32+d]  (8 MB)
__device__ float g_e1[65536];        // [(b*8+h)*1024 + n]
__device__ float g_e2[65536];
__device__ float g_C[64];            // per (b,h) softmax shift (upper bound of row max)

// ---------------- packed fp32x2 helpers (FFMA2 via PTX) ----------------------
__device__ __forceinline__ ull ffma2(ull a, ull b, ull c) {
    ull d;
    asm("fma.rn.f32x2 %0, %1, %2, %3;" : "=l"(d) : "l"(a), "l"(b), "l"(c));
    return d;
}
__device__ __forceinline__ ull packf2(float x) {
    ull d;
    asm("mov.b64 %0, {%1, %1};" : "=l"(d) : "f"(x));
    return d;
}
__device__ __forceinline__ void unpackf2(ull v, float& lo, float& hi) {
    asm("mov.b64 {%0, %1}, %2;" : "=f"(lo), "=f"(hi) : "l"(v));
}

// ---------------- Kernel A: Wh = X @ W  (8192 x 256 x 256 GEMM) --------------
// C[m][c] = sum_k X[m][k] * W[c>>5][k][c&31]
__global__ __launch_bounds__(256) void gemm_wh_k(const float* __restrict__ X,
                                                 const float* __restrict__ W) {
    __shared__ __align__(16) float As[16][64];   // [k][m]
    __shared__ __align__(16) float Bs[16][64];   // [k][c]
    const int bm = blockIdx.x;   // 128 tiles of 64 rows
    const int bn = blockIdx.y;   // 4 tiles of 64 cols
    const int t  = threadIdx.x;
    const int ty = t >> 4;       // 0..15 -> 4 rows each
    const int tx = t & 15;       // 0..15 -> 4 cols each

    ull acc[4][2];
#pragma unroll
    for (int i = 0; i < 4; i++) { acc[i][0] = 0ull; acc[i][1] = 0ull; }

    for (int k0 = 0; k0 < 256; k0 += 16) {
        {   // load A tile 64x16 (transposed into As[k][m])
            int r  = t >> 2;
            int kc = (t & 3) * 4;
            float4 v = *reinterpret_cast<const float4*>(
                X + ((size_t)bm * 64 + r) * 256 + k0 + kc);
            As[kc + 0][r] = v.x; As[kc + 1][r] = v.y;
            As[kc + 2][r] = v.z; As[kc + 3][r] = v.w;
        }
        {   // load B tile 16x64
            int kk = t >> 4;
            int cc = (t & 15) * 4;
            int c  = bn * 64 + cc;
            *reinterpret_cast<float4*>(&Bs[kk][cc]) =
                *reinterpret_cast<const float4*>(
                    W + ((size_t)(c >> 5) * 256 + k0 + kk) * 32 + (c & 31));
        }
        __syncthreads();
#pragma unroll
        for (int k = 0; k < 16; k++) {
            float4   av = *reinterpret_cast<const float4*>(&As[k][ty * 4]);
            longlong2 bv = *reinterpret_cast<const longlong2*>(&Bs[k][tx * 4]);
            ull a0 = packf2(av.x), a1 = packf2(av.y), a2 = packf2(av.z), a3 = packf2(av.w);
            acc[0][0] = ffma2(a0, (ull)bv.x, acc[0][0]); acc[0][1] = ffma2(a0, (ull)bv.y, acc[0][1]);
            acc[1][0] = ffma2(a1, (ull)bv.x, acc[1][0]); acc[1][1] = ffma2(a1, (ull)bv.y, acc[1][1]);
            acc[2][0] = ffma2(a2, (ull)bv.x, acc[2][0]); acc[2][1] = ffma2(a2, (ull)bv.y, acc[2][1]);
            acc[3][0] = ffma2(a3, (ull)bv.x, acc[3][0]); acc[3][1] = ffma2(a3, (ull)bv.y, acc[3][1]);
        }
        __syncthreads();
    }
#pragma unroll
    for (int i = 0; i < 4; i++) {
        float4 o;
        unpackf2(acc[i][0], o.x, o.y);
        unpackf2(acc[i][1], o.z, o.w);
        *reinterpret_cast<float4*>(
            g_Wh + ((size_t)bm * 64 + ty * 4 + i) * 256 + bn * 64 + tx * 4) = o;
    }
}

// ---------------- Kernel B: e1/e2 per (b,h,n): dot(Wh, a1/a2) ----------------
__global__ __launch_bounds__(256) void calc_e_k(const float* __restrict__ a) {
    const int T    = blockIdx.x * 8 + (threadIdx.x >> 5);  // 0..65535  = (b*8+h)*1024 + n
    const int lane = threadIdx.x & 31;
    const int n    = T & 1023;
    const int bh   = T >> 10;
    const int h    = bh & 7;
    const int b    = bh >> 3;

    float v  = g_Wh[((size_t)b * 1024 + n) * 256 + h * 32 + lane];
    float e1 = v * a[h * 64 + lane];
    float e2 = v * a[h * 64 + 32 + lane];
#pragma unroll
    for (int off = 16; off; off >>= 1) {
        e1 += __shfl_xor_sync(0xffffffffu, e1, off);
        e2 += __shfl_xor_sync(0xffffffffu, e2, off);
    }
    if (lane == 0) { g_e1[T] = e1; g_e2[T] = e2; }
}

// ---------------- Kernel C: per-(b,h) shift C = leaky(max e1 + max e2) -------
__global__ __launch_bounds__(256) void calc_c_k() {
    const int bh = blockIdx.x;     // 0..63
    const int t  = threadIdx.x;
    float m1 = -1e30f, m2 = -1e30f;
    for (int n = t; n < 1024; n += 256) {
        m1 = fmaxf(m1, g_e1[bh * 1024 + n]);
        m2 = fmaxf(m2, g_e2[bh * 1024 + n]);
    }
    __shared__ float s1[256], s2[256];
    s1[t] = m1; s2[t] = m2;
    __syncthreads();
    for (int o = 128; o; o >>= 1) {
        if (t < o) {
            s1[t] = fmaxf(s1[t], s1[t + o]);
            s2[t] = fmaxf(s2[t], s2[t + o]);
        }
        __syncthreads();
    }
    if (t == 0) {
        float s = s1[0] + s2[0];
        g_C[bh] = fmaxf(s, 0.2f * s);   // leaky of the upper bound, >= all row maxes
    }
}

// ---------------- Kernel D: fused masked-softmax + attn@Wh + epilogue --------
#define TI 32
#define TJ 16

__global__ __launch_bounds__(256) void gat_main_k(const int* __restrict__ adj,
                                                  const float* __restrict__ bias,
                                                  float* __restrict__ out) {
    const int b    = blockIdx.y;
    const int i0   = blockIdx.x * TI;
    const int t    = threadIdx.x;
    const int h    = t >> 5;      // warp == head
    const int lane = t & 31;
    const int ig   = lane >> 3;   // i-group: 4 groups of 8 rows
    const int dg   = lane & 7;    // d-group: 8 groups of 4 dims

    __shared__ __align__(16) float sWh[TJ][256];      // 16 KB
    __shared__ __align__(16) float sP[8][TJ][TI];     // 16 KB
    __shared__ __align__(16) float sE2[8][TJ];
    __shared__ __align__(16) float sDen[8][TI];

    const float Ch    = g_C[b * 8 + h];
    const float my_e1 = g_e1[(b * 8 + h) * 1024 + i0 + lane];   // p-phase row = lane
    const int4* __restrict__ adjRow = reinterpret_cast<const int4*>(
        adj + ((size_t)b << 20) + ((size_t)(i0 + lane) << 10));

    float den = 0.f;
    ull acc[16];
#pragma unroll
    for (int k = 0; k < 16; k++) acc[k] = 0ull;

    for (int j0 = 0; j0 < 1024; j0 += TJ) {
        __syncthreads();   // protect previous iteration's sWh/sP reads
        // cooperative sWh load: 16 rows x 256 floats = 1024 float4, 4 per thread
#pragma unroll
        for (int k = 0; k < 4; k++) {
            int idx = t + k * 256;
            int r   = idx >> 6;
            int c   = idx & 63;
            reinterpret_cast<float4*>(sWh[r])[c] =
                reinterpret_cast<const float4*>(
                    g_Wh + (((size_t)b << 10) + j0 + r) * 256)[c];
        }
        if (lane < TJ)   // warp-local e2 chunk
            sE2[h][lane] = g_e2[(b * 8 + h) * 1024 + j0 + lane];
        __syncthreads();

        // ---- p phase: thread (h, i=lane) computes p for 16 j's ----
        const int4* ap = adjRow + (j0 >> 2);
#pragma unroll
        for (int c4 = 0; c4 < 4; c4++) {
            int4 m  = ap[c4];
            int  jb = c4 * 4;
            {
                float s = my_e1 + sE2[h][jb + 0];
                float l = fmaxf(s, 0.2f * s);
                float p = m.x ? __expf(l - Ch) : 0.f;
                den += p; sP[h][jb + 0][lane] = p;
            }
            {
                float s = my_e1 + sE2[h][jb + 1];
                float l = fmaxf(s, 0.2f * s);
                float p = m.y ? __expf(l - Ch) : 0.f;
                den += p; sP[h][jb + 1][lane] = p;
            }
            {
                float s = my_e1 + sE2[h][jb + 2];
                float l = fmaxf(s, 0.2f * s);
                float p = m.z ? __expf(l - Ch) : 0.f;
                den += p; sP[h][jb + 2][lane] = p;
            }
            {
                float s = my_e1 + sE2[h][jb + 3];
                float l = fmaxf(s, 0.2f * s);
                float p = m.w ? __expf(l - Ch) : 0.f;
                den += p; sP[h][jb + 3][lane] = p;
            }
        }
        __syncwarp();   // sP[h][*][*] produced and consumed within warp h only

        // ---- FMA phase: rank-16 update of [8 i x 4 d] accumulators ----
#pragma unroll
        for (int jj = 0; jj < TJ; jj++) {
            longlong2 w = *reinterpret_cast<const longlong2*>(&sWh[jj][h * 32 + dg * 4]);
            float4 pA = *reinterpret_cast<const float4*>(&sP[h][jj][ig * 8]);
            float4 pB = *reinterpret_cast<const float4*>(&sP[h][jj][ig * 8 + 4]);
            ull p0 = packf2(pA.x), p1 = packf2(pA.y), p2 = packf2(pA.z), p3 = packf2(pA.w);
            ull p4 = packf2(pB.x), p5 = packf2(pB.y), p6 = packf2(pB.z), p7 = packf2(pB.w);
            acc[0]  = ffma2(p0, (ull)w.x, acc[0]);  acc[1]  = ffma2(p0, (ull)w.y, acc[1]);
            acc[2]  = ffma2(p1, (ull)w.x, acc[2]);  acc[3]  = ffma2(p1, (ull)w.y, acc[3]);
            acc[4]  = ffma2(p2, (ull)w.x, acc[4]);  acc[5]  = ffma2(p2, (ull)w.y, acc[5]);
            acc[6]  = ffma2(p3, (ull)w.x, acc[6]);  acc[7]  = ffma2(p3, (ull)w.y, acc[7]);
            acc[8]  = ffma2(p4, (ull)w.x, acc[8]);  acc[9]  = ffma2(p4, (ull)w.y, acc[9]);
            acc[10] = ffma2(p5, (ull)w.x, acc[10]); acc[11] = ffma2(p5, (ull)w.y, acc[11]);
            acc[12] = ffma2(p6, (ull)w.x, acc[12]); acc[13] = ffma2(p6, (ull)w.y, acc[13]);
            acc[14] = ffma2(p7, (ull)w.x, acc[14]); acc[15] = ffma2(p7, (ull)w.y, acc[15]);
        }
    }

    sDen[h][lane] = den;
    __syncthreads();

    // epilogue: out = relu(num/den + bias)
    float4 bi = *reinterpret_cast<const float4*>(bias + h * 32 + dg * 4);
#pragma unroll
    for (int k = 0; k < 8; k++) {
        int   i = ig * 8 + k;
        float r = 1.0f / sDen[h][i];
        float v0, v1, v2, v3;
        unpackf2(acc[2 * k],     v0, v1);
        unpackf2(acc[2 * k + 1], v2, v3);
        float4 o;
        o.x = fmaxf(v0 * r + bi.x, 0.f);
        o.y = fmaxf(v1 * r + bi.y, 0.f);
        o.z = fmaxf(v2 * r + bi.z, 0.f);
        o.w = fmaxf(v3 * r + bi.w, 0.f);
        *reinterpret_cast<float4*>(
            out + (((size_t)b << 10) + i0 + i) * 256 + h * 32 + dg * 4) = o;
    }
}

// ---------------- launcher ---------------------------------------------------
extern "C" void kernel_launch(void* const* d_in, const int* in_sizes, int n_in,
                              void* d_out, int out_size) {
    const float* nf   = (const float*)d_in[0];   // (8,1024,256)
    const int*   adj  = (const int*)d_in[1];     // (8,1024,1024)
    const float* W    = (const float*)d_in[2];   // (8,256,32)
    const float* a    = (const float*)d_in[3];   // (8,64)
    const float* bias = (const float*)d_in[4];   // (256,)
    float*       out  = (float*)d_out;           // (8,1024,256)

    gemm_wh_k<<<dim3(128, 4), 256>>>(nf, W);
    calc_e_k<<<8192, 256>>>(a);
    calc_c_k<<<64, 256>>>();
    gat_main_k<<<dim3(32, 8), 256>>>(adj, bias, out);
}

// round 2
// speedup vs baseline: 1.0548x; 1.0548x over previous
#include <cuda_runtime.h>
#include <cstdint>
#include <cstddef>

typedef unsigned long long ull;

// ---------------- scratch (static device globals; no runtime alloc) ----------
__device__ float g_Wh[8192 * 256];   // [b*1024+n][h*32+d]  (8 MB)
__device__ float g_e1[65536];        // [(b*8+h)*1024 + n]
__device__ float g_e2[65536];
__device__ float g_C[64];            // per (b,h) softmax shift (upper bound of row max)

// ---------------- packed fp32x2 helpers (FFMA2 via PTX) ----------------------
__device__ __forceinline__ ull ffma2(ull a, ull b, ull c) {
    ull d;
    asm("fma.rn.f32x2 %0, %1, %2, %3;" : "=l"(d) : "l"(a), "l"(b), "l"(c));
    return d;
}
__device__ __forceinline__ ull packf2(float x) {
    ull d;
    asm("mov.b64 %0, {%1, %1};" : "=l"(d) : "f"(x));
    return d;
}
__device__ __forceinline__ void unpackf2(ull v, float& lo, float& hi) {
    asm("mov.b64 {%0, %1}, %2;" : "=f"(lo), "=f"(hi) : "l"(v));
}

// ---------------- Kernel A: Wh = X @ W  (8192 x 256 x 256 GEMM) --------------
// C[m][c] = sum_k X[m][k] * W[c>>5][k][c&31]
__global__ __launch_bounds__(256) void gemm_wh_k(const float* __restrict__ X,
                                                 const float* __restrict__ W) {
    __shared__ __align__(16) float As[16][64];   // [k][m]
    __shared__ __align__(16) float Bs[16][64];   // [k][c]
    const int bm = blockIdx.x;   // 128 tiles of 64 rows
    const int bn = blockIdx.y;   // 4 tiles of 64 cols
    const int t  = threadIdx.x;
    const int ty = t >> 4;       // 0..15 -> 4 rows each
    const int tx = t & 15;       // 0..15 -> 4 cols each

    ull acc[4][2];
#pragma unroll
    for (int i = 0; i < 4; i++) { acc[i][0] = 0ull; acc[i][1] = 0ull; }

    for (int k0 = 0; k0 < 256; k0 += 16) {
        {   // load A tile 64x16 (transposed into As[k][m])
            int r  = t >> 2;
            int kc = (t & 3) * 4;
            float4 v = *reinterpret_cast<const float4*>(
                X + ((size_t)bm * 64 + r) * 256 + k0 + kc);
            As[kc + 0][r] = v.x; As[kc + 1][r] = v.y;
            As[kc + 2][r] = v.z; As[kc + 3][r] = v.w;
        }
        {   // load B tile 16x64
            int kk = t >> 4;
            int cc = (t & 15) * 4;
            int c  = bn * 64 + cc;
            *reinterpret_cast<float4*>(&Bs[kk][cc]) =
                *reinterpret_cast<const float4*>(
                    W + ((size_t)(c >> 5) * 256 + k0 + kk) * 32 + (c & 31));
        }
        __syncthreads();
#pragma unroll
        for (int k = 0; k < 16; k++) {
            float4   av = *reinterpret_cast<const float4*>(&As[k][ty * 4]);
            longlong2 bv = *reinterpret_cast<const longlong2*>(&Bs[k][tx * 4]);
            ull a0 = packf2(av.x), a1 = packf2(av.y), a2 = packf2(av.z), a3 = packf2(av.w);
            acc[0][0] = ffma2(a0, (ull)bv.x, acc[0][0]); acc[0][1] = ffma2(a0, (ull)bv.y, acc[0][1]);
            acc[1][0] = ffma2(a1, (ull)bv.x, acc[1][0]); acc[1][1] = ffma2(a1, (ull)bv.y, acc[1][1]);
            acc[2][0] = ffma2(a2, (ull)bv.x, acc[2][0]); acc[2][1] = ffma2(a2, (ull)bv.y, acc[2][1]);
            acc[3][0] = ffma2(a3, (ull)bv.x, acc[3][0]); acc[3][1] = ffma2(a3, (ull)bv.y, acc[3][1]);
        }
        __syncthreads();
    }
#pragma unroll
    for (int i = 0; i < 4; i++) {
        float4 o;
        unpackf2(acc[i][0], o.x, o.y);
        unpackf2(acc[i][1], o.z, o.w);
        *reinterpret_cast<float4*>(
            g_Wh + ((size_t)bm * 64 + ty * 4 + i) * 256 + bn * 64 + tx * 4) = o;
    }
}

// ---------------- Kernel B: e1/e2 per (b,h,n): dot(Wh, a1/a2) ----------------
__global__ __launch_bounds__(256) void calc_e_k(const float* __restrict__ a) {
    const int T    = blockIdx.x * 8 + (threadIdx.x >> 5);  // 0..65535  = (b*8+h)*1024 + n
    const int lane = threadIdx.x & 31;
    const int n    = T & 1023;
    const int bh   = T >> 10;
    const int h    = bh & 7;
    const int b    = bh >> 3;

    float v  = g_Wh[((size_t)b * 1024 + n) * 256 + h * 32 + lane];
    float e1 = v * a[h * 64 + lane];
    float e2 = v * a[h * 64 + 32 + lane];
#pragma unroll
    for (int off = 16; off; off >>= 1) {
        e1 += __shfl_xor_sync(0xffffffffu, e1, off);
        e2 += __shfl_xor_sync(0xffffffffu, e2, off);
    }
    if (lane == 0) { g_e1[T] = e1; g_e2[T] = e2; }
}

// ---------------- Kernel C: per-(b,h) shift C = leaky(max e1 + max e2) -------
__global__ __launch_bounds__(256) void calc_c_k() {
    const int bh = blockIdx.x;     // 0..63
    const int t  = threadIdx.x;
    float m1 = -1e30f, m2 = -1e30f;
    for (int n = t; n < 1024; n += 256) {
        m1 = fmaxf(m1, g_e1[bh * 1024 + n]);
        m2 = fmaxf(m2, g_e2[bh * 1024 + n]);
    }
    __shared__ float s1[256], s2[256];
    s1[t] = m1; s2[t] = m2;
    __syncthreads();
    for (int o = 128; o; o >>= 1) {
        if (t < o) {
            s1[t] = fmaxf(s1[t], s1[t + o]);
            s2[t] = fmaxf(s2[t], s2[t + o]);
        }
        __syncthreads();
    }
    if (t == 0) {
        float s = s1[0] + s2[0];
        g_C[bh] = fmaxf(s, 0.2f * s);   // leaky of the upper bound, >= all row maxes
    }
}

// ---------------- Kernel D: fused masked-softmax + attn@Wh + epilogue --------
#define TI 32
#define TJ 16

__global__ __launch_bounds__(256) void gat_main_k(const int* __restrict__ adj,
                                                  const float* __restrict__ bias,
                                                  float* __restrict__ out) {
    const int b    = blockIdx.y;
    const int i0   = blockIdx.x * TI;
    const int t    = threadIdx.x;
    const int h    = t >> 5;      // warp == head
    const int lane = t & 31;
    const int ig   = lane >> 3;   // i-group: 4 groups of 8 rows
    const int dg   = lane & 7;    // d-group: 8 groups of 4 dims

    __shared__ __align__(16) float sWh[TJ][256];      // 16 KB
    __shared__ __align__(16) float sP[8][TJ][TI];     // 16 KB
    __shared__ __align__(16) float sE2[8][TJ];
    __shared__ __align__(16) float sDen[8][TI];

    const float Ch    = g_C[b * 8 + h];
    const float my_e1 = g_e1[(b * 8 + h) * 1024 + i0 + lane];   // p-phase row = lane
    const int4* __restrict__ adjRow = reinterpret_cast<const int4*>(
        adj + ((size_t)b << 20) + ((size_t)(i0 + lane) << 10));

    float den = 0.f;
    ull acc[16];
#pragma unroll
    for (int k = 0; k < 16; k++) acc[k] = 0ull;

    for (int j0 = 0; j0 < 1024; j0 += TJ) {
        __syncthreads();   // protect previous iteration's sWh/sP reads
        // cooperative sWh load: 16 rows x 256 floats = 1024 float4, 4 per thread
#pragma unroll
        for (int k = 0; k < 4; k++) {
            int idx = t + k * 256;
            int r   = idx >> 6;
            int c   = idx & 63;
            reinterpret_cast<float4*>(sWh[r])[c] =
                reinterpret_cast<const float4*>(
                    g_Wh + (((size_t)b << 10) + j0 + r) * 256)[c];
        }
        if (lane < TJ)   // warp-local e2 chunk
            sE2[h][lane] = g_e2[(b * 8 + h) * 1024 + j0 + lane];
        __syncthreads();

        // ---- p phase: thread (h, i=lane) computes p for 16 j's ----
        const int4* ap = adjRow + (j0 >> 2);
#pragma unroll
        for (int c4 = 0; c4 < 4; c4++) {
            int4 m  = ap[c4];
            int  jb = c4 * 4;
            {
                float s = my_e1 + sE2[h][jb + 0];
                float l = fmaxf(s, 0.2f * s);
                float p = m.x ? __expf(l - Ch) : 0.f;
                den += p; sP[h][jb + 0][lane] = p;
            }
            {
                float s = my_e1 + sE2[h][jb + 1];
                float l = fmaxf(s, 0.2f * s);
                float p = m.y ? __expf(l - Ch) : 0.f;
                den += p; sP[h][jb + 1][lane] = p;
            }
            {
                float s = my_e1 + sE2[h][jb + 2];
                float l = fmaxf(s, 0.2f * s);
                float p = m.z ? __expf(l - Ch) : 0.f;
                den += p; sP[h][jb + 2][lane] = p;
            }
            {
                float s = my_e1 + sE2[h][jb + 3];
                float l = fmaxf(s, 0.2f * s);
                float p = m.w ? __expf(l - Ch) : 0.f;
                den += p; sP[h][jb + 3][lane] = p;
            }
        }
        __syncwarp();   // sP[h][*][*] produced and consumed within warp h only

        // ---- FMA phase: rank-16 update of [8 i x 4 d] accumulators ----
#pragma unroll
        for (int jj = 0; jj < TJ; jj++) {
            longlong2 w = *reinterpret_cast<const longlong2*>(&sWh[jj][h * 32 + dg * 4]);
            float4 pA = *reinterpret_cast<const float4*>(&sP[h][jj][ig * 8]);
            float4 pB = *reinterpret_cast<const float4*>(&sP[h][jj][ig * 8 + 4]);
            ull p0 = packf2(pA.x), p1 = packf2(pA.y), p2 = packf2(pA.z), p3 = packf2(pA.w);
            ull p4 = packf2(pB.x), p5 = packf2(pB.y), p6 = packf2(pB.z), p7 = packf2(pB.w);
            acc[0]  = ffma2(p0, (ull)w.x, acc[0]);  acc[1]  = ffma2(p0, (ull)w.y, acc[1]);
            acc[2]  = ffma2(p1, (ull)w.x, acc[2]);  acc[3]  = ffma2(p1, (ull)w.y, acc[3]);
            acc[4]  = ffma2(p2, (ull)w.x, acc[4]);  acc[5]  = ffma2(p2, (ull)w.y, acc[5]);
            acc[6]  = ffma2(p3, (ull)w.x, acc[6]);  acc[7]  = ffma2(p3, (ull)w.y, acc[7]);
            acc[8]  = ffma2(p4, (ull)w.x, acc[8]);  acc[9]  = ffma2(p4, (ull)w.y, acc[9]);
            acc[10] = ffma2(p5, (ull)w.x, acc[10]); acc[11] = ffma2(p5, (ull)w.y, acc[11]);
            acc[12] = ffma2(p6, (ull)w.x, acc[12]); acc[13] = ffma2(p6, (ull)w.y, acc[13]);
            acc[14] = ffma2(p7, (ull)w.x, acc[14]); acc[15] = ffma2(p7, (ull)w.y, acc[15]);
        }
    }

    sDen[h][lane] = den;
    __syncthreads();

    // epilogue: out = relu(num/den + bias)
    float4 bi = *reinterpret_cast<const float4*>(bias + h * 32 + dg * 4);
#pragma unroll
    for (int k = 0; k < 8; k++) {
        int   i = ig * 8 + k;
        float r = 1.0f / sDen[h][i];
        float v0, v1, v2, v3;
        unpackf2(acc[2 * k],     v0, v1);
        unpackf2(acc[2 * k + 1], v2, v3);
        float4 o;
        o.x = fmaxf(v0 * r + bi.x, 0.f);
        o.y = fmaxf(v1 * r + bi.y, 0.f);
        o.z = fmaxf(v2 * r + bi.z, 0.f);
        o.w = fmaxf(v3 * r + bi.w, 0.f);
        *reinterpret_cast<float4*>(
            out + (((size_t)b << 10) + i0 + i) * 256 + h * 32 + dg * 4) = o;
    }
}

// ---------------- launcher ---------------------------------------------------
extern "C" void kernel_launch(void* const* d_in, const int* in_sizes, int n_in,
                              void* d_out, int out_size) {
    const float* nf   = (const float*)d_in[0];   // (8,1024,256)
    const int*   adj  = (const int*)d_in[1];     // (8,1024,1024)
    const float* W    = (const float*)d_in[2];   // (8,256,32)
    const float* a    = (const float*)d_in[3];   // (8,64)
    const float* bias = (const float*)d_in[4];   // (256,)
    float*       out  = (float*)d_out;           // (8,1024,256)

    gemm_wh_k<<<dim3(128, 4), 256>>>(nf, W);
    calc_e_k<<<8192, 256>>>(a);
    calc_c_k<<<64, 256>>>();
    gat_main_k<<<dim3(32, 8), 256>>>(adj, bias, out);
}

// round 3
// speedup vs baseline: 1.1710x; 1.1101x over previous
#include <cuda_runtime.h>
#include <cstdint>
#include <cstddef>

typedef unsigned long long ull;

// ---------------- scratch (static device globals; no runtime alloc) ----------
__device__ __align__(16) float g_Wh[8192 * 256];   // [b*1024+n][h*32+d]  (8 MB)
__device__ __align__(16) float g_e1[65536];        // [(b*8+h)*1024 + n]
__device__ __align__(16) float g_e2[65536];
__device__ float g_C[64];                          // per (b,h) softmax shift
__device__ __align__(16) unsigned int g_adjbits[8 * 1024 * 32];  // 1 MB bitmask

// ---------------- packed fp32x2 helpers (FFMA2 via PTX) ----------------------
__device__ __forceinline__ ull ffma2(ull a, ull b, ull c) {
    ull d;
    asm("fma.rn.f32x2 %0, %1, %2, %3;" : "=l"(d) : "l"(a), "l"(b), "l"(c));
    return d;
}
__device__ __forceinline__ ull packf2(float x) {
    ull d;
    asm("mov.b64 %0, {%1, %1};" : "=l"(d) : "f"(x));
    return d;
}
__device__ __forceinline__ void unpackf2(ull v, float& lo, float& hi) {
    asm("mov.b64 {%0, %1}, %2;" : "=f"(lo), "=f"(hi) : "l"(v));
}

// ---------------- Kernel A: Wh = X @ W  (8192 x 256 x 256 GEMM) --------------
__global__ __launch_bounds__(256) void gemm_wh_k(const float* __restrict__ X,
                                                 const float* __restrict__ W) {
    __shared__ __align__(16) float As[16][64];
    __shared__ __align__(16) float Bs[16][64];
    const int bm = blockIdx.x;
    const int bn = blockIdx.y;
    const int t  = threadIdx.x;
    const int ty = t >> 4;
    const int tx = t & 15;

    ull acc[4][2];
#pragma unroll
    for (int i = 0; i < 4; i++) { acc[i][0] = 0ull; acc[i][1] = 0ull; }

    for (int k0 = 0; k0 < 256; k0 += 16) {
        {
            int r  = t >> 2;
            int kc = (t & 3) * 4;
            float4 v = *reinterpret_cast<const float4*>(
                X + ((size_t)bm * 64 + r) * 256 + k0 + kc);
            As[kc + 0][r] = v.x; As[kc + 1][r] = v.y;
            As[kc + 2][r] = v.z; As[kc + 3][r] = v.w;
        }
        {
            int kk = t >> 4;
            int cc = (t & 15) * 4;
            int c  = bn * 64 + cc;
            *reinterpret_cast<float4*>(&Bs[kk][cc]) =
                *reinterpret_cast<const float4*>(
                    W + ((size_t)(c >> 5) * 256 + k0 + kk) * 32 + (c & 31));
        }
        __syncthreads();
#pragma unroll
        for (int k = 0; k < 16; k++) {
            float4    av = *reinterpret_cast<const float4*>(&As[k][ty * 4]);
            longlong2 bv = *reinterpret_cast<const longlong2*>(&Bs[k][tx * 4]);
            ull a0 = packf2(av.x), a1 = packf2(av.y), a2 = packf2(av.z), a3 = packf2(av.w);
            acc[0][0] = ffma2(a0, (ull)bv.x, acc[0][0]); acc[0][1] = ffma2(a0, (ull)bv.y, acc[0][1]);
            acc[1][0] = ffma2(a1, (ull)bv.x, acc[1][0]); acc[1][1] = ffma2(a1, (ull)bv.y, acc[1][1]);
            acc[2][0] = ffma2(a2, (ull)bv.x, acc[2][0]); acc[2][1] = ffma2(a2, (ull)bv.y, acc[2][1]);
            acc[3][0] = ffma2(a3, (ull)bv.x, acc[3][0]); acc[3][1] = ffma2(a3, (ull)bv.y, acc[3][1]);
        }
        __syncthreads();
    }
#pragma unroll
    for (int i = 0; i < 4; i++) {
        float4 o;
        unpackf2(acc[i][0], o.x, o.y);
        unpackf2(acc[i][1], o.z, o.w);
        *reinterpret_cast<float4*>(
            g_Wh + ((size_t)bm * 64 + ty * 4 + i) * 256 + bn * 64 + tx * 4) = o;
    }
}

// ---------------- Kernel A2: bitpack adjacency (32 MB -> 1 MB) ---------------
__global__ __launch_bounds__(256) void bitpack_k(const int* __restrict__ adj) {
    const int w = blockIdx.x * 256 + threadIdx.x;     // word index, 262144 total
    const int4* p = reinterpret_cast<const int4*>(adj) + (size_t)w * 8;
    unsigned int bits = 0;
#pragma unroll
    for (int k = 0; k < 8; k++) {
        int4 v = p[k];
        bits |= (unsigned)(v.x != 0) << (k * 4 + 0);
        bits |= (unsigned)(v.y != 0) << (k * 4 + 1);
        bits |= (unsigned)(v.z != 0) << (k * 4 + 2);
        bits |= (unsigned)(v.w != 0) << (k * 4 + 3);
    }
    g_adjbits[w] = bits;
}

// ---------------- Kernel B: e1/e2 per (b,h,n) --------------------------------
__global__ __launch_bounds__(256) void calc_e_k(const float* __restrict__ a) {
    const int T    = blockIdx.x * 8 + (threadIdx.x >> 5);
    const int lane = threadIdx.x & 31;
    const int n    = T & 1023;
    const int bh   = T >> 10;
    const int h    = bh & 7;
    const int b    = bh >> 3;

    float v  = g_Wh[((size_t)b * 1024 + n) * 256 + h * 32 + lane];
    float e1 = v * a[h * 64 + lane];
    float e2 = v * a[h * 64 + 32 + lane];
#pragma unroll
    for (int off = 16; off; off >>= 1) {
        e1 += __shfl_xor_sync(0xffffffffu, e1, off);
        e2 += __shfl_xor_sync(0xffffffffu, e2, off);
    }
    if (lane == 0) { g_e1[T] = e1; g_e2[T] = e2; }
}

// ---------------- Kernel C: per-(b,h) shift ----------------------------------
__global__ __launch_bounds__(256) void calc_c_k() {
    const int bh = blockIdx.x;
    const int t  = threadIdx.x;
    float m1 = -1e30f, m2 = -1e30f;
    for (int n = t; n < 1024; n += 256) {
        m1 = fmaxf(m1, g_e1[bh * 1024 + n]);
        m2 = fmaxf(m2, g_e2[bh * 1024 + n]);
    }
    __shared__ float s1[256], s2[256];
    s1[t] = m1; s2[t] = m2;
    __syncthreads();
    for (int o = 128; o; o >>= 1) {
        if (t < o) {
            s1[t] = fmaxf(s1[t], s1[t + o]);
            s2[t] = fmaxf(s2[t], s2[t + o]);
        }
        __syncthreads();
    }
    if (t == 0) {
        float s = s1[0] + s2[0];
        g_C[bh] = fmaxf(s, 0.2f * s);
    }
}

// ---------------- Kernel D: fused masked-softmax + attn@Wh + epilogue --------
// Block: 256 threads = 8 warps (warp == head), 16 i-rows per block.
// Grid: (64 i-tiles, 8 b) = 512 blocks. No __syncthreads in the main loop.
// FMA mapping:  ig = lane>>3 (4 groups of 4 rows), dg = lane&7 (8 groups of 4 dims)
// p   mapping:  il = lane&15 (row), jh = lane>>4 (j-half: 8 j's each)
__global__ __launch_bounds__(256, 4) void gat_main_k(const float* __restrict__ bias,
                                                     float* __restrict__ out) {
    const int b    = blockIdx.y;
    const int i0   = blockIdx.x * 16;
    const int t    = threadIdx.x;
    const int h    = t >> 5;
    const int lane = t & 31;
    const int ig   = lane >> 3;
    const int dg   = lane & 7;
    const int il   = lane & 15;
    const int jh   = lane >> 4;

    __shared__ __align__(16) float2       sPd[2][8][16][16];  // (p,p) pairs, 32 KB
    __shared__ __align__(16) unsigned int sMask[16][32];      // 2 KB
    __shared__ float                      sDen[8][16];

    // cooperative mask load: 512 words, 2 per thread
    {
        int w   = t * 2;
        int row = w >> 5;
        int col = w & 31;
        *reinterpret_cast<uint2*>(&sMask[row][col]) =
            *reinterpret_cast<const uint2*>(
                &g_adjbits[((size_t)b * 1024 + i0 + row) * 32 + col]);
    }
    __syncthreads();   // only barrier; masks shared across head-warps

    const int   bh    = b * 8 + h;
    const float Ch    = g_C[bh];
    const float my_e1 = g_e1[bh * 1024 + i0 + il];
    const float* __restrict__ e2B = g_e2 + bh * 1024;
    const float* __restrict__ WhB = g_Wh + (((size_t)b << 10)) * 256 + h * 32;

    float den = 0.f;
    ull acc[8];
#pragma unroll
    for (int k = 0; k < 8; k++) acc[k] = 0ull;

#pragma unroll 2
    for (int j0 = 0; j0 < 1024; j0 += 16) {
        const int buf = (j0 >> 4) & 1;

        // ---- p phase: thread (h, il, jh) computes p for 8 j's ----
        unsigned int mbits = sMask[il][j0 >> 5] >> ((j0 & 16) + jh * 8);
        const float4* e2p = reinterpret_cast<const float4*>(e2B + j0 + jh * 8);
        float4 ea = e2p[0], eb = e2p[1];
#define DO_P(K, EV)                                                       \
        {                                                                 \
            float s = my_e1 + (EV);                                       \
            float l = fmaxf(s, 0.2f * s);                                 \
            float p = ((mbits >> (K)) & 1u) ? __expf(l - Ch) : 0.f;       \
            den += p;                                                     \
            sPd[buf][h][jh * 8 + (K)][il] = make_float2(p, p);            \
        }
        DO_P(0, ea.x) DO_P(1, ea.y) DO_P(2, ea.z) DO_P(3, ea.w)
        DO_P(4, eb.x) DO_P(5, eb.y) DO_P(6, eb.z) DO_P(7, eb.w)
#undef DO_P
        __syncwarp();   // sP produced/consumed within warp h only

        // ---- FMA phase: rank-16 update of [4 i x 4 d] accumulators ----
        const float* wrow = WhB + (size_t)j0 * 256 + dg * 4;
#pragma unroll
        for (int jj = 0; jj < 16; jj++) {
            longlong2 w2 = *reinterpret_cast<const longlong2*>(wrow + jj * 256);
            longlong2 pA = *reinterpret_cast<const longlong2*>(&sPd[buf][h][jj][ig * 4]);
            longlong2 pB = *reinterpret_cast<const longlong2*>(&sPd[buf][h][jj][ig * 4 + 2]);
            acc[0] = ffma2((ull)pA.x, (ull)w2.x, acc[0]);
            acc[1] = ffma2((ull)pA.x, (ull)w2.y, acc[1]);
            acc[2] = ffma2((ull)pA.y, (ull)w2.x, acc[2]);
            acc[3] = ffma2((ull)pA.y, (ull)w2.y, acc[3]);
            acc[4] = ffma2((ull)pB.x, (ull)w2.x, acc[4]);
            acc[5] = ffma2((ull)pB.x, (ull)w2.y, acc[5]);
            acc[6] = ffma2((ull)pB.y, (ull)w2.x, acc[6]);
            acc[7] = ffma2((ull)pB.y, (ull)w2.y, acc[7]);
        }
    }

    // combine den halves: row il total = den(jh=0) + den(jh=1)
    den += __shfl_xor_sync(0xffffffffu, den, 16);
    if (lane < 16) sDen[h][il] = den;
    __syncwarp();

    // epilogue: out = relu(num/den + bias)
    float4 bi = *reinterpret_cast<const float4*>(bias + h * 32 + dg * 4);
#pragma unroll
    for (int r = 0; r < 4; r++) {
        int   i  = ig * 4 + r;
        float rd = 1.0f / sDen[h][i];
        float v0, v1, v2, v3;
        unpackf2(acc[2 * r],     v0, v1);
        unpackf2(acc[2 * r + 1], v2, v3);
        float4 o;
        o.x = fmaxf(v0 * rd + bi.x, 0.f);
        o.y = fmaxf(v1 * rd + bi.y, 0.f);
        o.z = fmaxf(v2 * rd + bi.z, 0.f);
        o.w = fmaxf(v3 * rd + bi.w, 0.f);
        *reinterpret_cast<float4*>(
            out + (((size_t)b << 10) + i0 + i) * 256 + h * 32 + dg * 4) = o;
    }
}

// ---------------- launcher ---------------------------------------------------
extern "C" void kernel_launch(void* const* d_in, const int* in_sizes, int n_in,
                              void* d_out, int out_size) {
    const float* nf   = (const float*)d_in[0];   // (8,1024,256)
    const int*   adj  = (const int*)d_in[1];     // (8,1024,1024)
    const float* W    = (const float*)d_in[2];   // (8,256,32)
    const float* a    = (const float*)d_in[3];   // (8,64)
    const float* bias = (const float*)d_in[4];   // (256,)
    float*       out  = (float*)d_out;           // (8,1024,256)

    bitpack_k<<<1024, 256>>>(adj);
    gemm_wh_k<<<dim3(128, 4), 256>>>(nf, W);
    calc_e_k<<<8192, 256>>>(a);
    calc_c_k<<<64, 256>>>();
    gat_main_k<<<dim3(64, 8), 256>>>(bias, out);
}